// round 1
// baseline (speedup 1.0000x reference)
#include <cuda_runtime.h>
#include <math.h>

// Problem constants (fixed shapes from reference)
#define BB 16
#define HH 544
#define WW 960
#define NTOT (BB * HH * WW)          // 8,355,840
#define N4   (NTOT / 4)              // 2,088,960 float4 chunks
#define THREADS 256
#define ITEMS 4
#define BLOCKS (N4 / (THREADS * ITEMS))   // 2040 exactly

// Global accumulators: [0]=count, [1]=sum smooth_l1(dl - dlgt)*mf, [2]=sum smooth_l1(recon-lgt)*mf
__device__ double g_acc[3];

__device__ __forceinline__ float smooth_l1(float d) {
    float ad = fabsf(d);
    return (ad < 1.0f) ? 0.5f * d * d : ad - 0.5f;
}

__global__ void __launch_bounds__(THREADS)
reduce_kernel(const float* __restrict__ dl,
              const float* __restrict__ seg,
              const float* __restrict__ dlgt,
              const float* __restrict__ lgt)
{
    float cnt = 0.0f, sd = 0.0f, sr = 0.0f;

    const int stride = blockDim.x * gridDim.x;
    for (int i4 = blockIdx.x * blockDim.x + threadIdx.x; i4 < N4; i4 += stride) {
        const int idx = i4 * 4;
        const float4 dv = *reinterpret_cast<const float4*>(dl   + idx);
        const float4 lv = *reinterpret_cast<const float4*>(lgt  + idx);
        const float4 gv = *reinterpret_cast<const float4*>(dlgt + idx);

        // W divisible by 4 -> all 4 lanes of the float4 are in the same image row
        const int row   = idx / WW;
        const int wbase = idx - row * WW;
        const float* __restrict__ srow = seg + row * WW;

        #pragma unroll
        for (int k = 0; k < 4; k++) {
            const float d  = (&dv.x)[k];
            const float l  = (&lv.x)[k];
            const float dg = (&gv.x)[k];
            if (l > 0.0f) {
                cnt += 1.0f;
                // disparity smooth-L1 term
                sd += smooth_l1(d - dg);

                // horizontal bilinear warp of seg_r at (w - d), zeros padding
                const float sx = (float)(wbase + k) - d;
                const float x0 = floorf(sx);
                const float wx = sx - x0;
                const int x0i = (int)x0;
                const int x1i = x0i + 1;
                // d >= 0 so x0i <= w < W always; only lower bound needed for x0i,
                // both bounds for x1i (upper hits at d==0, w==W-1).
                const float g0 = ((unsigned)x0i < (unsigned)WW) ? __ldg(srow + x0i) : 0.0f;
                const float g1 = ((unsigned)x1i < (unsigned)WW) ? __ldg(srow + x1i) : 0.0f;
                const float warped = (1.0f - wx) * g0 + wx * g1;

                // sigmoid
                const float recon = 1.0f / (1.0f + __expf(-warped));
                sr += smooth_l1(recon - l);
            }
        }
    }

    // ---- block reduction (warp shuffles, then shared, then fp64 atomics) ----
    #pragma unroll
    for (int off = 16; off > 0; off >>= 1) {
        cnt += __shfl_down_sync(0xffffffffu, cnt, off);
        sd  += __shfl_down_sync(0xffffffffu, sd,  off);
        sr  += __shfl_down_sync(0xffffffffu, sr,  off);
    }

    __shared__ float s_cnt[THREADS / 32];
    __shared__ float s_sd [THREADS / 32];
    __shared__ float s_sr [THREADS / 32];

    const int lane = threadIdx.x & 31;
    const int wid  = threadIdx.x >> 5;
    if (lane == 0) { s_cnt[wid] = cnt; s_sd[wid] = sd; s_sr[wid] = sr; }
    __syncthreads();

    if (wid == 0) {
        cnt = (lane < THREADS / 32) ? s_cnt[lane] : 0.0f;
        sd  = (lane < THREADS / 32) ? s_sd [lane] : 0.0f;
        sr  = (lane < THREADS / 32) ? s_sr [lane] : 0.0f;
        #pragma unroll
        for (int off = 4; off > 0; off >>= 1) {
            cnt += __shfl_down_sync(0xffffffffu, cnt, off);
            sd  += __shfl_down_sync(0xffffffffu, sd,  off);
            sr  += __shfl_down_sync(0xffffffffu, sr,  off);
        }
        if (lane == 0) {
            atomicAdd(&g_acc[0], (double)cnt);
            atomicAdd(&g_acc[1], (double)sd);
            atomicAdd(&g_acc[2], (double)sr);
        }
    }
}

__global__ void finalize_kernel(float* __restrict__ out)
{
    const double cnt = g_acc[0];
    const double sd  = g_acc[1];
    const double sr  = g_acc[2];

    float loss = (float)(sd / cnt);
    if (isnan(loss)) loss = 0.0f;
    const float loss_recon = (float)(sr / cnt);
    out[0] = loss + 0.5f * loss_recon;

    // Reset accumulators so every kernel_launch call (incl. graph replays)
    // starts from a clean state.
    g_acc[0] = 0.0;
    g_acc[1] = 0.0;
    g_acc[2] = 0.0;
}

extern "C" void kernel_launch(void* const* d_in, const int* in_sizes, int n_in,
                              void* d_out, int out_size)
{
    const float* dl   = (const float*)d_in[0];
    const float* seg  = (const float*)d_in[1];
    const float* dlgt = (const float*)d_in[2];
    const float* lgt  = (const float*)d_in[3];
    float* out = (float*)d_out;

    reduce_kernel<<<BLOCKS, THREADS>>>(dl, seg, dlgt, lgt);
    finalize_kernel<<<1, 1>>>(out);
}

// round 2
// speedup vs baseline: 1.0491x; 1.0491x over previous
#include <cuda_runtime.h>
#include <math.h>

// Fixed problem shape
#define BB 16
#define HH 544
#define WW 960
#define ROWS_TOTAL (BB * HH)          // 8704 image rows
#define NRPB 4                        // rows per block
#define GRID (ROWS_TOTAL / NRPB)      // 2176 blocks (exact)
#define THREADS 256
#define F4_PER_ROW (WW / 4)           // 240 float4 per row
#define WORK (NRPB * F4_PER_ROW)      // 960 float4 work items per block

// Global accumulators: [0]=count, [1]=sum sl1(dl-dlgt)*m, [2]=sum sl1(recon-lgt)*m
__device__ double   g_acc[3];
__device__ unsigned g_done;

__device__ __forceinline__ float smooth_l1(float d) {
    float ad = fabsf(d);
    return (ad < 1.0f) ? 0.5f * d * d : ad - 0.5f;
}

__global__ void __launch_bounds__(THREADS)
fused_loss_kernel(const float* __restrict__ dl,
                  const float* __restrict__ seg,
                  const float* __restrict__ dlgt,
                  const float* __restrict__ lgt,
                  float* __restrict__ out)
{
    __shared__ float srow[NRPB][WW];   // 15.36 KB

    const int row0 = blockIdx.x * NRPB;

    // ---- Stage seg rows into shared memory (coalesced float4) ----
    for (int i = threadIdx.x; i < WORK; i += THREADS) {
        const int r = i / F4_PER_ROW;
        const int c = i - r * F4_PER_ROW;
        const float4 v = *reinterpret_cast<const float4*>(seg + (row0 + r) * WW + c * 4);
        *reinterpret_cast<float4*>(&srow[r][c * 4]) = v;
    }
    __syncthreads();

    // ---- Main accumulation ----
    float cnt = 0.0f, sd = 0.0f, sr = 0.0f;

    for (int i = threadIdx.x; i < WORK; i += THREADS) {
        const int r     = i / F4_PER_ROW;
        const int c4    = i - r * F4_PER_ROW;
        const int wbase = c4 * 4;
        const int idx   = (row0 + r) * WW + wbase;

        const float4 dv = *reinterpret_cast<const float4*>(dl   + idx);
        const float4 lv = *reinterpret_cast<const float4*>(lgt  + idx);
        const float4 gv = *reinterpret_cast<const float4*>(dlgt + idx);
        const float* __restrict__ s = srow[r];

        #pragma unroll
        for (int k = 0; k < 4; k++) {
            const float d  = (&dv.x)[k];
            const float l  = (&lv.x)[k];
            const float dg = (&gv.x)[k];
            if (l > 0.0f) {
                cnt += 1.0f;
                sd  += smooth_l1(d - dg);

                // horizontal bilinear warp of seg at (w - d), zeros padding
                const float sx = (float)(wbase + k) - d;
                const float x0 = floorf(sx);
                const float wx = sx - x0;
                const int x0i = (int)x0;
                const int x1i = x0i + 1;
                const float g0 = ((unsigned)x0i < (unsigned)WW) ? s[x0i] : 0.0f;
                const float g1 = ((unsigned)x1i < (unsigned)WW) ? s[x1i] : 0.0f;
                const float warped = (1.0f - wx) * g0 + wx * g1;

                const float recon = 1.0f / (1.0f + __expf(-warped));
                sr += smooth_l1(recon - l);
            }
        }
    }

    // ---- Block reduction: warp shuffles -> shared -> fp64 atomics ----
    #pragma unroll
    for (int off = 16; off > 0; off >>= 1) {
        cnt += __shfl_down_sync(0xffffffffu, cnt, off);
        sd  += __shfl_down_sync(0xffffffffu, sd,  off);
        sr  += __shfl_down_sync(0xffffffffu, sr,  off);
    }

    __shared__ float s_cnt[THREADS / 32];
    __shared__ float s_sd [THREADS / 32];
    __shared__ float s_sr [THREADS / 32];

    const int lane = threadIdx.x & 31;
    const int wid  = threadIdx.x >> 5;
    if (lane == 0) { s_cnt[wid] = cnt; s_sd[wid] = sd; s_sr[wid] = sr; }
    __syncthreads();

    if (wid == 0) {
        cnt = (lane < THREADS / 32) ? s_cnt[lane] : 0.0f;
        sd  = (lane < THREADS / 32) ? s_sd [lane] : 0.0f;
        sr  = (lane < THREADS / 32) ? s_sr [lane] : 0.0f;
        #pragma unroll
        for (int off = 4; off > 0; off >>= 1) {
            cnt += __shfl_down_sync(0xffffffffu, cnt, off);
            sd  += __shfl_down_sync(0xffffffffu, sd,  off);
            sr  += __shfl_down_sync(0xffffffffu, sr,  off);
        }
        if (lane == 0) {
            atomicAdd(&g_acc[0], (double)cnt);
            atomicAdd(&g_acc[1], (double)sd);
            atomicAdd(&g_acc[2], (double)sr);

            // ---- Last-block finalize (fused; no second kernel) ----
            __threadfence();
            const unsigned ticket = atomicAdd(&g_done, 1u);
            if (ticket == GRID - 1) {
                const double tc = g_acc[0];
                const double ts = g_acc[1];
                const double tr = g_acc[2];

                float loss = (float)(ts / tc);
                if (isnan(loss)) loss = 0.0f;
                const float loss_recon = (float)(tr / tc);
                out[0] = loss + 0.5f * loss_recon;

                // Reset state for the next (graph-replayed) call
                g_acc[0] = 0.0;
                g_acc[1] = 0.0;
                g_acc[2] = 0.0;
                g_done   = 0u;
            }
        }
    }
}

extern "C" void kernel_launch(void* const* d_in, const int* in_sizes, int n_in,
                              void* d_out, int out_size)
{
    const float* dl   = (const float*)d_in[0];
    const float* seg  = (const float*)d_in[1];
    const float* dlgt = (const float*)d_in[2];
    const float* lgt  = (const float*)d_in[3];
    float* out = (float*)d_out;

    fused_loss_kernel<<<GRID, THREADS>>>(dl, seg, dlgt, lgt, out);
}